// round 10
// baseline (speedup 1.0000x reference)
#include <cuda_runtime.h>
#include <cstdint>
#include <cfloat>
#include <math.h>

#define Bb 32
#define Nn 64
#define Mm 64
#define Cc 64
#define C1d 16
#define Hh 256
#define TH 768
#define FD 912
#define GD 2992

// ---------------- device scratch ----------------
__device__ float  g_P[(size_t)Bb * Nn * Mm * TH];   // input proj of every states row [131072][768]
__device__ float  g_F[(size_t)Bb * Nn * FD];        // f [2048][912]
__device__ float  g_XW1[(size_t)Bb * Nn * TH];      // gru1d input proj [2048][768]
__device__ float2 g_W2dup[(size_t)Hh * TH];         // gru2d Whh, [k][768] duplicated pairs
__device__ float  g_Whh1T[Hh * TH];                 // [256][768]
__device__ float  g_fc1Wt[GD * Hh];                 // [2992][256]
__device__ float  g_G[Bb * GD];
__device__ float  g_H2[Bb * Hh];
__device__ int    g_perm1[Nn * Mm];
__device__ int    g_perm2[Nn * Nn];

// ---------------- helpers ----------------
__device__ __forceinline__ unsigned long long pack2(float lo, float hi) {
    unsigned long long r;
    asm("mov.b64 %0, {%1, %2};" : "=l"(r) : "f"(lo), "f"(hi));
    return r;
}
__device__ __forceinline__ float2 unpack2(unsigned long long v) {
    float2 r;
    asm("mov.b64 {%0, %1}, %2;" : "=f"(r.x), "=f"(r.y) : "l"(v));
    return r;
}
__device__ __forceinline__ void ffma2(unsigned long long& d, unsigned long long a, unsigned long long b) {
    asm("fma.rn.f32x2 %0, %1, %2, %0;" : "+l"(d) : "l"(a), "l"(b));
}
__device__ __forceinline__ float tanh_fast(float x) {
    float y; asm("tanh.approx.f32 %0, %1;" : "=f"(y) : "f"(x)); return y;
}
__device__ __forceinline__ float sig_fast(float x) {
    return fmaf(tanh_fast(x * 0.5f), 0.5f, 0.5f);
}
__device__ __forceinline__ void cp_async16(uint32_t dst, const void* src) {
    asm volatile("cp.async.cg.shared.global [%0], [%1], 16;" :: "r"(dst), "l"(src));
}

// ---------------- both perm conversions in one kernel (int64 vs int32 detect) ----------------
__global__ void conv_perm2_kernel(const int* __restrict__ r1, const int* __restrict__ r2) {
    const int* raw = blockIdx.x ? r2 : r1;
    int* out = blockIdx.x ? g_perm2 : g_perm1;
    const int n = Nn * Mm;   // 4096 both
    __shared__ int notI64;
    if (threadIdx.x == 0) notI64 = 0;
    __syncthreads();
    for (int i = threadIdx.x; i < n / 2; i += blockDim.x)
        if (raw[2 * i + 1] != 0) notI64 = 1;
    __syncthreads();
    if (notI64) { for (int i = threadIdx.x; i < n; i += blockDim.x) out[i] = raw[i]; }
    else        { for (int i = threadIdx.x; i < n; i += blockDim.x) out[i] = raw[2 * i]; }
}

// ---------------- transpose in[R][C] -> out[C][R] ----------------
__global__ void transpose_kernel(const float* __restrict__ in, float* __restrict__ out, int R, int C) {
    int idx = blockIdx.x * 256 + threadIdx.x;
    if (idx < R * C) { int r = idx / C, c = idx % C; out[c * R + r] = in[idx]; }
}

// ---------------- gru2d weight transpose with pair duplication ----------------
// in: Whh [768][256]; out: g_W2dup[k][o] = (w, w)
__global__ void dup_transpose_kernel(const float* __restrict__ in) {
    int idx = blockIdx.x * 256 + threadIdx.x;
    if (idx < TH * Hh) {
        int o = idx / Hh, k = idx % Hh;
        float w = in[idx];
        g_W2dup[(size_t)k * TH + o] = make_float2(w, w);
    }
}

// ---------------- stats over states + x1 copy -> F[:, 0:400] ----------------
__global__ void stats_kernel(const float* __restrict__ states, const float* __restrict__ x1) {
    int bi = blockIdx.x;               // b*64 + i
    int b = bi >> 6, i = bi & 63;
    int c = threadIdx.x;               // 64 threads
    float* fr = g_F + (size_t)bi * FD;

    float mx = -FLT_MAX, mn = FLT_MAX, sm = 0.0f;
    for (int n = 0; n < Nn; ++n) {
        float v = states[(((size_t)(b * Nn + n)) * Mm + i) * Cc + c];
        mx = fmaxf(mx, v); mn = fminf(mn, v); sm += v;
    }
    fr[C1d + c]          = mx;
    fr[C1d + Cc + c]     = sm * (1.0f / 64.0f);
    fr[C1d + 2 * Cc + c] = mn;

    mx = -FLT_MAX; mn = FLT_MAX; sm = 0.0f;
    for (int m = 0; m < Mm; ++m) {
        float v = states[(((size_t)(b * Nn + i)) * Mm + m) * Cc + c];
        mx = fmaxf(mx, v); mn = fminf(mn, v); sm += v;
    }
    fr[C1d + 3 * Cc + c] = mx;
    fr[C1d + 4 * Cc + c] = sm * (1.0f / 64.0f);
    fr[C1d + 5 * Cc + c] = mn;

    if (c < C1d) fr[c] = x1[bi * C1d + c];
}

// ---------------- SGEMM 128x64 tile: C[M][N] = A[M][K] @ B[N][K]^T + bias[N] ----------------
__global__ void gemm128_kernel(const float* __restrict__ A, const float* __restrict__ Bm,
                               const float* __restrict__ bias, float* __restrict__ Cm,
                               int K, int Ndim) {
    __shared__ __align__(16) float As[16][132];
    __shared__ __align__(16) float Bs[16][68];
    const int tx = threadIdx.x, ty = threadIdx.y;
    const int tid = ty * 16 + tx;
    const int m0 = blockIdx.y * 128, n0 = blockIdx.x * 64;

    float acc[8][4];
    #pragma unroll
    for (int i = 0; i < 8; ++i)
        #pragma unroll
        for (int jj = 0; jj < 4; ++jj) acc[i][jj] = 0.0f;

    for (int k0 = 0; k0 < K; k0 += 16) {
        #pragma unroll
        for (int e = 0; e < 8; ++e) {
            int idx = tid + e * 256;
            int r = idx >> 4, kk = idx & 15;
            As[kk][r] = A[(size_t)(m0 + r) * K + k0 + kk];
        }
        #pragma unroll
        for (int e = 0; e < 4; ++e) {
            int idx = tid + e * 256;
            int r = idx >> 4, kk = idx & 15;
            Bs[kk][r] = Bm[(size_t)(n0 + r) * K + k0 + kk];
        }
        __syncthreads();
        #pragma unroll
        for (int kk = 0; kk < 16; ++kk) {
            float4 a0 = *reinterpret_cast<const float4*>(&As[kk][ty * 8]);
            float4 a1 = *reinterpret_cast<const float4*>(&As[kk][ty * 8 + 4]);
            float4 b4 = *reinterpret_cast<const float4*>(&Bs[kk][tx * 4]);
            float av[8] = {a0.x, a0.y, a0.z, a0.w, a1.x, a1.y, a1.z, a1.w};
            float bv[4] = {b4.x, b4.y, b4.z, b4.w};
            #pragma unroll
            for (int i = 0; i < 8; ++i)
                #pragma unroll
                for (int jj = 0; jj < 4; ++jj)
                    acc[i][jj] = fmaf(av[i], bv[jj], acc[i][jj]);
        }
        __syncthreads();
    }
    float4 bia = *reinterpret_cast<const float4*>(&bias[n0 + tx * 4]);
    #pragma unroll
    for (int i = 0; i < 8; ++i) {
        float4 v = make_float4(acc[i][0] + bia.x, acc[i][1] + bia.y,
                               acc[i][2] + bia.z, acc[i][3] + bia.w);
        *reinterpret_cast<float4*>(&Cm[(size_t)(m0 + ty * 8 + i) * Ndim + n0 + tx * 4]) = v;
    }
}

// ---------------- persistent 2D GRU: G=32 seqs/CTA, gate-split passes ----------------
// smem (floats): sh_h [256][36] @0 | sh_xw [32][768] @9216 | sh_row [2048] @33792
//                sh_acc float2[2][16][257] @35840  → total 209152 B
__global__ void __launch_bounds__(256)
gru2d_kernel(const float* __restrict__ bhh) {
    const int dir  = blockIdx.x >> 6;           // 0: sd1, 1: sd2
    const int seq0 = (blockIdx.x & 63) * 32;
    const int j    = threadIdx.x;

    extern __shared__ __align__(16) float dyn[];
    float  (*sh_h)[36] = (float (*)[36])dyn;                 // [256][36]
    float*  sh_xw  = dyn + 9216;                             // [32][768]
    int*    sh_row = (int*)(dyn + 33792);                    // [32][64]
    float2* sh_acc = (float2*)(dyn + 35840);                 // [2][16][257]

    #pragma unroll
    for (int g = 0; g < 36; ++g) sh_h[j][g] = 0.0f;

    for (int e = j; e < 32 * 64; e += 256) {
        int g = e >> 6, t = e & 63;
        int s = seq0 + g;
        int b = s >> 6, n = s & 63;
        sh_row[e] = (dir == 0)
            ? (b * Nn + n) * Mm + g_perm1[n * Mm + t]
            : (b * Nn + g_perm2[n * Nn + t]) * Mm + n;
    }

    const unsigned long long bR2 = pack2(bhh[j], bhh[j]);
    const unsigned long long bZ2 = pack2(bhh[Hh + j], bhh[Hh + j]);
    const unsigned long long bN2 = pack2(bhh[2 * Hh + j], bhh[2 * Hh + j]);

    const int my_g = j >> 3;                   // 32 rows, 8 threads per row
    const int my_c = j & 7;
    uint32_t xw_dst_base = (uint32_t)__cvta_generic_to_shared(sh_xw + my_g * TH);
    __syncthreads();

    for (int t = 0; t < 64; ++t) {
        // async-gather the 32 precomputed xw rows (32 x 3KB) into smem
        {
            const float* src_row = g_P + (size_t)sh_row[my_g * 64 + t] * TH;
            #pragma unroll
            for (int i = 0; i < 24; ++i) {
                int c16 = my_c + 8 * i;
                cp_async16(xw_dst_base + c16 * 16, src_row + c16 * 4);
            }
            asm volatile("cp.async.commit_group;");
        }

        // ----- passes R (p=0) and Z (p=1): 16 accs each, park raw sums in smem -----
        #pragma unroll
        for (int p = 0; p < 2; ++p) {
            unsigned long long acc[16];
            const unsigned long long binit = (p == 0) ? bR2 : bZ2;
            #pragma unroll
            for (int g = 0; g < 16; ++g) acc[g] = binit;

            const float2* wd = g_W2dup + p * Hh + j;   // [k][768] dup pairs, col p*256+j
            #pragma unroll 8
            for (int k = 0; k < Hh; ++k) {
                float2 wp = wd[(size_t)k * TH];
                unsigned long long w2 = *reinterpret_cast<const unsigned long long*>(&wp);
                const ulonglong2* hrow = reinterpret_cast<const ulonglong2*>(&sh_h[k][0]);
                #pragma unroll
                for (int q = 0; q < 8; ++q) {
                    ulonglong2 hp = hrow[q];
                    ffma2(acc[2 * q],     w2, hp.x);
                    ffma2(acc[2 * q + 1], w2, hp.y);
                }
            }
            #pragma unroll
            for (int g = 0; g < 16; ++g)
                *reinterpret_cast<unsigned long long*>(&sh_acc[(p * 16 + g) * 257 + j]) = acc[g];
        }

        // ----- pass N: keep ghN in registers -----
        unsigned long long ghN[16];
        #pragma unroll
        for (int g = 0; g < 16; ++g) ghN[g] = bN2;
        {
            const float2* wd = g_W2dup + 2 * Hh + j;
            #pragma unroll 8
            for (int k = 0; k < Hh; ++k) {
                float2 wp = wd[(size_t)k * TH];
                unsigned long long w2 = *reinterpret_cast<const unsigned long long*>(&wp);
                const ulonglong2* hrow = reinterpret_cast<const ulonglong2*>(&sh_h[k][0]);
                #pragma unroll
                for (int q = 0; q < 8; ++q) {
                    ulonglong2 hp = hrow[q];
                    ffma2(ghN[2 * q],     w2, hp.x);
                    ffma2(ghN[2 * q + 1], w2, hp.y);
                }
            }
        }

        asm volatile("cp.async.wait_group 0;" ::: "memory");
        __syncthreads();

        float hnew[32];
        #pragma unroll
        for (int gg = 0; gg < 16; ++gg) {
            float2 aR = sh_acc[gg * 257 + j];            // own slot, no barrier needed
            float2 aZ = sh_acc[(16 + gg) * 257 + j];
            float2 hN = unpack2(ghN[gg]);
            const float* x0 = sh_xw + (2 * gg) * TH + j;
            const float* x1 = sh_xw + (2 * gg + 1) * TH + j;
            float r0 = sig_fast(aR.x + x0[0]);
            float z0 = sig_fast(aZ.x + x0[Hh]);
            float n0 = tanh_fast(x0[2 * Hh] + r0 * hN.x);
            hnew[2 * gg]     = (1.0f - z0) * n0 + z0 * sh_h[j][2 * gg];
            float r1 = sig_fast(aR.y + x1[0]);
            float z1 = sig_fast(aZ.y + x1[Hh]);
            float n1 = tanh_fast(x1[2 * Hh] + r1 * hN.y);
            hnew[2 * gg + 1] = (1.0f - z1) * n1 + z1 * sh_h[j][2 * gg + 1];
        }
        __syncthreads();
        #pragma unroll
        for (int g = 0; g < 32; ++g) sh_h[j][g] = hnew[g];
        __syncthreads();
    }

    const int off = (dir == 0) ? (C1d + 6 * Cc) : (C1d + 6 * Cc + Hh);  // 400 / 656
    #pragma unroll
    for (int g = 0; g < 32; ++g)
        g_F[(size_t)(seq0 + g) * FD + off + j] = sh_h[j][g];
}

// ---------------- 1D GRU: 32 blocks x 256 threads, float4 weight rows ----------------
__global__ void gru1d_kernel(const float* __restrict__ bhh) {
    const int b = blockIdx.x;
    const int tid = threadIdx.x;
    __shared__ float sh_h[Hh];
    __shared__ float sums[TH];
    sh_h[tid] = 0.0f;
    const float br = bhh[tid], bz = bhh[Hh + tid], bn = bhh[2 * Hh + tid];
    __syncthreads();

    for (int t = 0; t < 64; ++t) {
        if (tid < 192) {
            float4 acc = make_float4(0.0f, 0.0f, 0.0f, 0.0f);
            const float* wbase = g_Whh1T + 4 * tid;
            #pragma unroll 8
            for (int k = 0; k < Hh; ++k) {
                float4 w = *reinterpret_cast<const float4*>(wbase + k * TH);
                float hv = sh_h[k];
                acc.x = fmaf(w.x, hv, acc.x);
                acc.y = fmaf(w.y, hv, acc.y);
                acc.z = fmaf(w.z, hv, acc.z);
                acc.w = fmaf(w.w, hv, acc.w);
            }
            *reinterpret_cast<float4*>(&sums[4 * tid]) = acc;
        }
        __syncthreads();

        const float* xw = g_XW1 + (size_t)(b * 64 + t) * TH;  // includes bih
        float r = sig_fast(xw[tid] + sums[tid] + br);
        float z = sig_fast(xw[Hh + tid] + sums[Hh + tid] + bz);
        float n = tanh_fast(xw[2 * Hh + tid] + r * (sums[2 * Hh + tid] + bn));
        float hnew = (1.0f - z) * n + z * sh_h[tid];
        __syncthreads();
        sh_h[tid] = hnew;
        __syncthreads();
    }
    g_G[(size_t)b * GD + 3 * FD + tid] = sh_h[tid];
}

// ---------------- g = [f.max(1), f.mean(1), f.min(1)] -> G[:, 0:2736] ----------------
__global__ void finalg_kernel() {
    const int b = blockIdx.x;
    for (int c = threadIdx.x; c < FD; c += 256) {
        float mx = -FLT_MAX, mn = FLT_MAX, sm = 0.0f;
        for (int n = 0; n < Nn; ++n) {
            float v = g_F[(size_t)(b * Nn + n) * FD + c];
            mx = fmaxf(mx, v); mn = fminf(mn, v); sm += v;
        }
        g_G[(size_t)b * GD + c]          = mx;
        g_G[(size_t)b * GD + FD + c]     = sm * (1.0f / 64.0f);
        g_G[(size_t)b * GD + 2 * FD + c] = mn;
    }
}

// ---------------- fc1 (relu) ----------------
__global__ void fc1_kernel(const float* __restrict__ fc1_b) {
    const int b = blockIdx.x;
    const int o = threadIdx.x;
    __shared__ float sg[GD];
    for (int k = o; k < GD; k += 256) sg[k] = g_G[(size_t)b * GD + k];
    __syncthreads();
    float acc = fc1_b[o];
    #pragma unroll 4
    for (int k = 0; k < GD; ++k) acc = fmaf(sg[k], g_fc1Wt[(size_t)k * Hh + o], acc);
    g_H2[b * Hh + o] = fmaxf(acc, 0.0f);
}

// ---------------- fc2 ----------------
__global__ void fc2_kernel(const float* __restrict__ fc2_W, const float* __restrict__ fc2_b,
                           float* __restrict__ out) {
    const int b = blockIdx.x;
    const int j = threadIdx.x;
    __shared__ float red[256];
    red[j] = g_H2[b * Hh + j] * fc2_W[j];
    __syncthreads();
    for (int s = 128; s > 0; s >>= 1) {
        if (j < s) red[j] += red[j + s];
        __syncthreads();
    }
    if (j == 0) out[b] = red[0] + fc2_b[0];
}

// ---------------- launch ----------------
extern "C" void kernel_launch(void* const* d_in, const int* in_sizes, int n_in,
                              void* d_out, int out_size) {
    const float* x1     = (const float*)d_in[0];
    const float* states = (const float*)d_in[1];
    const int*   perm1r = (const int*)d_in[2];
    const int*   perm2r = (const int*)d_in[3];
    const float* g2Wih  = (const float*)d_in[4];
    const float* g2Whh  = (const float*)d_in[5];
    const float* g2bih  = (const float*)d_in[6];
    const float* g2bhh  = (const float*)d_in[7];
    const float* g1Wih  = (const float*)d_in[8];
    const float* g1Whh  = (const float*)d_in[9];
    const float* g1bih  = (const float*)d_in[10];
    const float* g1bhh  = (const float*)d_in[11];
    const float* fc1W   = (const float*)d_in[12];
    const float* fc1b   = (const float*)d_in[13];
    const float* fc2W   = (const float*)d_in[14];
    const float* fc2b   = (const float*)d_in[15];
    float* out = (float*)d_out;

    float *whh1T, *fc1Wt, *xw1, *Fbuf, *Pbuf;
    cudaGetSymbolAddress((void**)&whh1T, g_Whh1T);
    cudaGetSymbolAddress((void**)&fc1Wt, g_fc1Wt);
    cudaGetSymbolAddress((void**)&xw1,   g_XW1);
    cudaGetSymbolAddress((void**)&Fbuf,  g_F);
    cudaGetSymbolAddress((void**)&Pbuf,  g_P);

    const int GRU2D_SMEM = 35840 * 4 + 2 * 16 * 257 * 8;   // 209152 B
    cudaFuncSetAttribute(gru2d_kernel, cudaFuncAttributeMaxDynamicSharedMemorySize, GRU2D_SMEM);

    // 1
    dup_transpose_kernel<<<(TH * Hh + 255) / 256, 256>>>(g2Whh);
    // 2: P = states @ g2Wih^T + g2bih   (M=131072, N=768, K=64)
    {
        dim3 g(TH / 64, (Bb * Nn * Mm) / 128);
        gemm128_kernel<<<g, dim3(16, 16)>>>(states, g2Wih, g2bih, Pbuf, Cc, TH);
    }
    // 3
    conv_perm2_kernel<<<2, 256>>>(perm1r, perm2r);
    // 4 — ncu target (-s 5 -c 1; 2 harness launches precede ours)
    gru2d_kernel<<<128, 256, GRU2D_SMEM>>>(g2bhh);
    // 5
    stats_kernel<<<Bb * Nn, 64>>>(states, x1);
    // 6
    transpose_kernel<<<(TH * Hh + 255) / 256, 256>>>(g1Whh, whh1T, TH, Hh);
    // 7: XW1 = F @ g1Wih^T + g1bih   (M=2048, N=768, K=912)
    {
        dim3 g(TH / 64, (Bb * Nn) / 128);
        gemm128_kernel<<<g, dim3(16, 16)>>>(Fbuf, g1Wih, g1bih, xw1, FD, TH);
    }
    // 8
    gru1d_kernel<<<Bb, Hh>>>(g1bhh);
    // 9
    finalg_kernel<<<Bb, 256>>>();
    // 10
    transpose_kernel<<<(Hh * GD + 255) / 256, 256>>>(fc1W, fc1Wt, Hh, GD);
    // 11
    fc1_kernel<<<Bb, Hh>>>(fc1b);
    // 12
    fc2_kernel<<<Bb, 256>>>(fc2W, fc2b, out);
}

// round 11
// speedup vs baseline: 1.3016x; 1.3016x over previous
#include <cuda_runtime.h>
#include <cstdint>
#include <cfloat>
#include <math.h>

#define Bb 32
#define Nn 64
#define Mm 64
#define Cc 64
#define C1d 16
#define Hh 256
#define TH 768
#define FD 912
#define GD 2992

// ---------------- device scratch ----------------
__device__ float  g_P[(size_t)Bb * Nn * Mm * TH];   // input proj of every states row [131072][768]
__device__ float  g_F[(size_t)Bb * Nn * FD];        // f [2048][912]
__device__ float  g_XW1[(size_t)Bb * Nn * TH];      // gru1d input proj [2048][768]
__device__ float2 g_W2dup[(size_t)Hh * TH];         // gru2d Whh, [k][768] duplicated pairs
__device__ float  g_Whh1T[Hh * TH];                 // [256][768]
__device__ float  g_fc1Wt[GD * Hh];                 // [2992][256]
__device__ float  g_G[Bb * GD];
__device__ float  g_H2[Bb * Hh];
__device__ int    g_perm1[Nn * Mm];
__device__ int    g_perm2[Nn * Nn];

// ---------------- helpers ----------------
__device__ __forceinline__ float2 unpack2(unsigned long long v) {
    float2 r;
    asm("mov.b64 {%0, %1}, %2;" : "=f"(r.x), "=f"(r.y) : "l"(v));
    return r;
}
__device__ __forceinline__ unsigned long long pack2(float lo, float hi) {
    unsigned long long r;
    asm("mov.b64 %0, {%1, %2};" : "=l"(r) : "f"(lo), "f"(hi));
    return r;
}
__device__ __forceinline__ void ffma2(unsigned long long& d, unsigned long long a, unsigned long long b) {
    asm("fma.rn.f32x2 %0, %1, %2, %0;" : "+l"(d) : "l"(a), "l"(b));
}
__device__ __forceinline__ float tanh_fast(float x) {
    float y; asm("tanh.approx.f32 %0, %1;" : "=f"(y) : "f"(x)); return y;
}
__device__ __forceinline__ float sig_fast(float x) {
    return fmaf(tanh_fast(x * 0.5f), 0.5f, 0.5f);
}
__device__ __forceinline__ void cp_async16(uint32_t dst, const void* src) {
    asm volatile("cp.async.cg.shared.global [%0], [%1], 16;" :: "r"(dst), "l"(src));
}

// ---------------- both perm conversions in one kernel (int64 vs int32 detect) ----------------
__global__ void conv_perm2_kernel(const int* __restrict__ r1, const int* __restrict__ r2) {
    const int* raw = blockIdx.x ? r2 : r1;
    int* out = blockIdx.x ? g_perm2 : g_perm1;
    const int n = Nn * Mm;   // 4096 both
    __shared__ int notI64;
    if (threadIdx.x == 0) notI64 = 0;
    __syncthreads();
    for (int i = threadIdx.x; i < n / 2; i += blockDim.x)
        if (raw[2 * i + 1] != 0) notI64 = 1;
    __syncthreads();
    if (notI64) { for (int i = threadIdx.x; i < n; i += blockDim.x) out[i] = raw[i]; }
    else        { for (int i = threadIdx.x; i < n; i += blockDim.x) out[i] = raw[2 * i]; }
}

// ---------------- transpose in[R][C] -> out[C][R] ----------------
__global__ void transpose_kernel(const float* __restrict__ in, float* __restrict__ out, int R, int C) {
    int idx = blockIdx.x * 256 + threadIdx.x;
    if (idx < R * C) { int r = idx / C, c = idx % C; out[c * R + r] = in[idx]; }
}

// ---------------- gru2d weight transpose with pair duplication ----------------
// in: Whh [768][256]; out: g_W2dup[k][o] = (w, w)
__global__ void dup_transpose_kernel(const float* __restrict__ in) {
    int idx = blockIdx.x * 256 + threadIdx.x;
    if (idx < TH * Hh) {
        int o = idx / Hh, k = idx % Hh;
        float w = in[idx];
        g_W2dup[(size_t)k * TH + o] = make_float2(w, w);
    }
}

// ---------------- stats over states + x1 copy -> F[:, 0:400] ----------------
__global__ void stats_kernel(const float* __restrict__ states, const float* __restrict__ x1) {
    int bi = blockIdx.x;               // b*64 + i
    int b = bi >> 6, i = bi & 63;
    int c = threadIdx.x;               // 64 threads
    float* fr = g_F + (size_t)bi * FD;

    float mx = -FLT_MAX, mn = FLT_MAX, sm = 0.0f;
    for (int n = 0; n < Nn; ++n) {
        float v = states[(((size_t)(b * Nn + n)) * Mm + i) * Cc + c];
        mx = fmaxf(mx, v); mn = fminf(mn, v); sm += v;
    }
    fr[C1d + c]          = mx;
    fr[C1d + Cc + c]     = sm * (1.0f / 64.0f);
    fr[C1d + 2 * Cc + c] = mn;

    mx = -FLT_MAX; mn = FLT_MAX; sm = 0.0f;
    for (int m = 0; m < Mm; ++m) {
        float v = states[(((size_t)(b * Nn + i)) * Mm + m) * Cc + c];
        mx = fmaxf(mx, v); mn = fminf(mn, v); sm += v;
    }
    fr[C1d + 3 * Cc + c] = mx;
    fr[C1d + 4 * Cc + c] = sm * (1.0f / 64.0f);
    fr[C1d + 5 * Cc + c] = mn;

    if (c < C1d) fr[c] = x1[bi * C1d + c];
}

// ---------------- SGEMM 128x64 tile: C[M][N] = A[M][K] @ B[N][K]^T + bias[N] ----------------
__global__ void gemm128_kernel(const float* __restrict__ A, const float* __restrict__ Bm,
                               const float* __restrict__ bias, float* __restrict__ Cm,
                               int K, int Ndim) {
    __shared__ __align__(16) float As[16][132];
    __shared__ __align__(16) float Bs[16][68];
    const int tx = threadIdx.x, ty = threadIdx.y;
    const int tid = ty * 16 + tx;
    const int m0 = blockIdx.y * 128, n0 = blockIdx.x * 64;

    float acc[8][4];
    #pragma unroll
    for (int i = 0; i < 8; ++i)
        #pragma unroll
        for (int jj = 0; jj < 4; ++jj) acc[i][jj] = 0.0f;

    for (int k0 = 0; k0 < K; k0 += 16) {
        #pragma unroll
        for (int e = 0; e < 8; ++e) {
            int idx = tid + e * 256;
            int r = idx >> 4, kk = idx & 15;
            As[kk][r] = A[(size_t)(m0 + r) * K + k0 + kk];
        }
        #pragma unroll
        for (int e = 0; e < 4; ++e) {
            int idx = tid + e * 256;
            int r = idx >> 4, kk = idx & 15;
            Bs[kk][r] = Bm[(size_t)(n0 + r) * K + k0 + kk];
        }
        __syncthreads();
        #pragma unroll
        for (int kk = 0; kk < 16; ++kk) {
            float4 a0 = *reinterpret_cast<const float4*>(&As[kk][ty * 8]);
            float4 a1 = *reinterpret_cast<const float4*>(&As[kk][ty * 8 + 4]);
            float4 b4 = *reinterpret_cast<const float4*>(&Bs[kk][tx * 4]);
            float av[8] = {a0.x, a0.y, a0.z, a0.w, a1.x, a1.y, a1.z, a1.w};
            float bv[4] = {b4.x, b4.y, b4.z, b4.w};
            #pragma unroll
            for (int i = 0; i < 8; ++i)
                #pragma unroll
                for (int jj = 0; jj < 4; ++jj)
                    acc[i][jj] = fmaf(av[i], bv[jj], acc[i][jj]);
        }
        __syncthreads();
    }
    float4 bia = *reinterpret_cast<const float4*>(&bias[n0 + tx * 4]);
    #pragma unroll
    for (int i = 0; i < 8; ++i) {
        float4 v = make_float4(acc[i][0] + bia.x, acc[i][1] + bia.y,
                               acc[i][2] + bia.z, acc[i][3] + bia.w);
        *reinterpret_cast<float4*>(&Cm[(size_t)(m0 + ty * 8 + i) * Ndim + n0 + tx * 4]) = v;
    }
}

// ---------------- persistent 2D GRU: G=32 seqs/CTA, 512 threads, single pass ----------------
// Threads tid<256 own lane-pairs 0..7 (seqs 0..15); tid>=256 own pairs 8..15 (seqs 16..31).
// smem: h[256][36] + xw[32][768] + rows[32][64] = 143360 B
__global__ void __launch_bounds__(512)
gru2d_kernel(const float* __restrict__ bhh) {
    const int dir  = blockIdx.x >> 6;           // 0: sd1, 1: sd2
    const int seq0 = (blockIdx.x & 63) * 32;
    const int tid  = threadIdx.x;
    const int j    = tid & 255;                 // hidden index
    const int half = tid >> 8;                  // 0 or 1

    extern __shared__ __align__(16) float dyn[];
    float (*sh_h)[36] = (float (*)[36])dyn;              // [256][36]
    float* sh_xw  = dyn + 256 * 36;                      // [32][768]
    int*   sh_row = (int*)(dyn + 256 * 36 + 32 * TH);    // [32][64]

    if (half == 0) {
        #pragma unroll
        for (int g = 0; g < 36; ++g) sh_h[j][g] = 0.0f;
    }

    for (int e = tid; e < 32 * 64; e += 512) {
        int g = e >> 6, t = e & 63;
        int s = seq0 + g;
        int b = s >> 6, n = s & 63;
        sh_row[e] = (dir == 0)
            ? (b * Nn + n) * Mm + g_perm1[n * Mm + t]
            : (b * Nn + g_perm2[n * Nn + t]) * Mm + n;
    }

    const unsigned long long bR2 = pack2(bhh[j], bhh[j]);
    const unsigned long long bZ2 = pack2(bhh[Hh + j], bhh[Hh + j]);
    const unsigned long long bN2 = pack2(bhh[2 * Hh + j], bhh[2 * Hh + j]);

    const int my_g = tid >> 4;                  // 32 rows, 16 threads per row
    const int my_c = tid & 15;
    uint32_t xw_dst_base = (uint32_t)__cvta_generic_to_shared(sh_xw + my_g * TH);
    __syncthreads();

    for (int t = 0; t < 64; ++t) {
        // async-gather the 32 precomputed xw rows (32 x 3KB) into smem
        {
            const float* src_row = g_P + (size_t)sh_row[my_g * 64 + t] * TH;
            #pragma unroll
            for (int i = 0; i < 12; ++i) {
                int c16 = my_c + 16 * i;
                cp_async16(xw_dst_base + c16 * 16, src_row + c16 * 4);
            }
            asm volatile("cp.async.commit_group;");
        }

        // ----- recurrent matvec for this half's 8 lane-pairs (16 seqs) -----
        unsigned long long accR[8], accZ[8], ghN[8];
        #pragma unroll
        for (int g = 0; g < 8; ++g) { accR[g] = bR2; accZ[g] = bZ2; ghN[g] = bN2; }

        const float2* wd = g_W2dup + j;
        const int hoff = half * 8;              // ulonglong2 quads 4*half..4*half+3
        #pragma unroll 4
        for (int k = 0; k < Hh; ++k) {
            float2 wrp = wd[(size_t)k * TH];
            float2 wzp = wd[(size_t)k * TH + Hh];
            float2 wnp = wd[(size_t)k * TH + 2 * Hh];
            unsigned long long wr2 = *reinterpret_cast<const unsigned long long*>(&wrp);
            unsigned long long wz2 = *reinterpret_cast<const unsigned long long*>(&wzp);
            unsigned long long wn2 = *reinterpret_cast<const unsigned long long*>(&wnp);
            const ulonglong2* hrow = reinterpret_cast<const ulonglong2*>(&sh_h[k][hoff * 2]);
            #pragma unroll
            for (int q = 0; q < 4; ++q) {
                ulonglong2 hp = hrow[q];        // local pairs 2q, 2q+1
                ffma2(accR[2 * q],     wr2, hp.x);
                ffma2(accZ[2 * q],     wz2, hp.x);
                ffma2(ghN[2 * q],      wn2, hp.x);
                ffma2(accR[2 * q + 1], wr2, hp.y);
                ffma2(accZ[2 * q + 1], wz2, hp.y);
                ffma2(ghN[2 * q + 1],  wn2, hp.y);
            }
        }

        asm volatile("cp.async.wait_group 0;" ::: "memory");
        __syncthreads();

        float hnew[16];
        #pragma unroll
        for (int gg = 0; gg < 8; ++gg) {
            int gp = hoff + gg;                 // global pair index
            const float* x0 = sh_xw + (2 * gp) * TH + j;
            const float* x1 = sh_xw + (2 * gp + 1) * TH + j;
            float2 aR = unpack2(accR[gg]);
            float2 aZ = unpack2(accZ[gg]);
            float2 hN = unpack2(ghN[gg]);
            float r0 = sig_fast(aR.x + x0[0]);
            float z0 = sig_fast(aZ.x + x0[Hh]);
            float n0 = tanh_fast(x0[2 * Hh] + r0 * hN.x);
            hnew[2 * gg]     = (1.0f - z0) * n0 + z0 * sh_h[j][2 * gp];
            float r1 = sig_fast(aR.y + x1[0]);
            float z1 = sig_fast(aZ.y + x1[Hh]);
            float n1 = tanh_fast(x1[2 * Hh] + r1 * hN.y);
            hnew[2 * gg + 1] = (1.0f - z1) * n1 + z1 * sh_h[j][2 * gp + 1];
        }
        __syncthreads();
        #pragma unroll
        for (int g = 0; g < 16; ++g) sh_h[j][hoff * 2 + g] = hnew[g];
        __syncthreads();
    }

    const int off = (dir == 0) ? (C1d + 6 * Cc) : (C1d + 6 * Cc + Hh);  // 400 / 656
    #pragma unroll
    for (int g = 0; g < 16; ++g)
        g_F[(size_t)(seq0 + 16 * half + g) * FD + off + j] = sh_h[j][16 * half + g];
}

// ---------------- 1D GRU: 32 blocks x 256 threads, float4 weight rows ----------------
__global__ void gru1d_kernel(const float* __restrict__ bhh) {
    const int b = blockIdx.x;
    const int tid = threadIdx.x;
    __shared__ float sh_h[Hh];
    __shared__ float sums[TH];
    sh_h[tid] = 0.0f;
    const float br = bhh[tid], bz = bhh[Hh + tid], bn = bhh[2 * Hh + tid];
    __syncthreads();

    for (int t = 0; t < 64; ++t) {
        if (tid < 192) {
            float4 acc = make_float4(0.0f, 0.0f, 0.0f, 0.0f);
            const float* wbase = g_Whh1T + 4 * tid;
            #pragma unroll 8
            for (int k = 0; k < Hh; ++k) {
                float4 w = *reinterpret_cast<const float4*>(wbase + k * TH);
                float hv = sh_h[k];
                acc.x = fmaf(w.x, hv, acc.x);
                acc.y = fmaf(w.y, hv, acc.y);
                acc.z = fmaf(w.z, hv, acc.z);
                acc.w = fmaf(w.w, hv, acc.w);
            }
            *reinterpret_cast<float4*>(&sums[4 * tid]) = acc;
        }
        __syncthreads();

        const float* xw = g_XW1 + (size_t)(b * 64 + t) * TH;  // includes bih
        float r = sig_fast(xw[tid] + sums[tid] + br);
        float z = sig_fast(xw[Hh + tid] + sums[Hh + tid] + bz);
        float n = tanh_fast(xw[2 * Hh + tid] + r * (sums[2 * Hh + tid] + bn));
        float hnew = (1.0f - z) * n + z * sh_h[tid];
        __syncthreads();
        sh_h[tid] = hnew;
        __syncthreads();
    }
    g_G[(size_t)b * GD + 3 * FD + tid] = sh_h[tid];
}

// ---------------- g = [f.max(1), f.mean(1), f.min(1)] -> G[:, 0:2736] ----------------
__global__ void finalg_kernel() {
    const int b = blockIdx.x;
    for (int c = threadIdx.x; c < FD; c += 256) {
        float mx = -FLT_MAX, mn = FLT_MAX, sm = 0.0f;
        for (int n = 0; n < Nn; ++n) {
            float v = g_F[(size_t)(b * Nn + n) * FD + c];
            mx = fmaxf(mx, v); mn = fminf(mn, v); sm += v;
        }
        g_G[(size_t)b * GD + c]          = mx;
        g_G[(size_t)b * GD + FD + c]     = sm * (1.0f / 64.0f);
        g_G[(size_t)b * GD + 2 * FD + c] = mn;
    }
}

// ---------------- fc1 (relu) ----------------
__global__ void fc1_kernel(const float* __restrict__ fc1_b) {
    const int b = blockIdx.x;
    const int o = threadIdx.x;
    __shared__ float sg[GD];
    for (int k = o; k < GD; k += 256) sg[k] = g_G[(size_t)b * GD + k];
    __syncthreads();
    float acc = fc1_b[o];
    #pragma unroll 4
    for (int k = 0; k < GD; ++k) acc = fmaf(sg[k], g_fc1Wt[(size_t)k * Hh + o], acc);
    g_H2[b * Hh + o] = fmaxf(acc, 0.0f);
}

// ---------------- fc2 ----------------
__global__ void fc2_kernel(const float* __restrict__ fc2_W, const float* __restrict__ fc2_b,
                           float* __restrict__ out) {
    const int b = blockIdx.x;
    const int j = threadIdx.x;
    __shared__ float red[256];
    red[j] = g_H2[b * Hh + j] * fc2_W[j];
    __syncthreads();
    for (int s = 128; s > 0; s >>= 1) {
        if (j < s) red[j] += red[j + s];
        __syncthreads();
    }
    if (j == 0) out[b] = red[0] + fc2_b[0];
}

// ---------------- launch ----------------
extern "C" void kernel_launch(void* const* d_in, const int* in_sizes, int n_in,
                              void* d_out, int out_size) {
    const float* x1     = (const float*)d_in[0];
    const float* states = (const float*)d_in[1];
    const int*   perm1r = (const int*)d_in[2];
    const int*   perm2r = (const int*)d_in[3];
    const float* g2Wih  = (const float*)d_in[4];
    const float* g2Whh  = (const float*)d_in[5];
    const float* g2bih  = (const float*)d_in[6];
    const float* g2bhh  = (const float*)d_in[7];
    const float* g1Wih  = (const float*)d_in[8];
    const float* g1Whh  = (const float*)d_in[9];
    const float* g1bih  = (const float*)d_in[10];
    const float* g1bhh  = (const float*)d_in[11];
    const float* fc1W   = (const float*)d_in[12];
    const float* fc1b   = (const float*)d_in[13];
    const float* fc2W   = (const float*)d_in[14];
    const float* fc2b   = (const float*)d_in[15];
    float* out = (float*)d_out;

    float *whh1T, *fc1Wt, *xw1, *Fbuf, *Pbuf;
    cudaGetSymbolAddress((void**)&whh1T, g_Whh1T);
    cudaGetSymbolAddress((void**)&fc1Wt, g_fc1Wt);
    cudaGetSymbolAddress((void**)&xw1,   g_XW1);
    cudaGetSymbolAddress((void**)&Fbuf,  g_F);
    cudaGetSymbolAddress((void**)&Pbuf,  g_P);

    const int GRU2D_SMEM = (256 * 36 + 32 * TH + 32 * 64) * 4;   // 143360
    cudaFuncSetAttribute(gru2d_kernel, cudaFuncAttributeMaxDynamicSharedMemorySize, GRU2D_SMEM);

    // 1
    dup_transpose_kernel<<<(TH * Hh + 255) / 256, 256>>>(g2Whh);
    // 2: P = states @ g2Wih^T + g2bih   (M=131072, N=768, K=64)
    {
        dim3 g(TH / 64, (Bb * Nn * Mm) / 128);
        gemm128_kernel<<<g, dim3(16, 16)>>>(states, g2Wih, g2bih, Pbuf, Cc, TH);
    }
    // 3
    conv_perm2_kernel<<<2, 256>>>(perm1r, perm2r);
    // 4 — ncu target (-s 5 -c 1; 2 harness launches precede ours)
    gru2d_kernel<<<128, 512, GRU2D_SMEM>>>(g2bhh);
    // 5
    stats_kernel<<<Bb * Nn, 64>>>(states, x1);
    // 6
    transpose_kernel<<<(TH * Hh + 255) / 256, 256>>>(g1Whh, whh1T, TH, Hh);
    // 7: XW1 = F @ g1Wih^T + g1bih   (M=2048, N=768, K=912)
    {
        dim3 g(TH / 64, (Bb * Nn) / 128);
        gemm128_kernel<<<g, dim3(16, 16)>>>(Fbuf, g1Wih, g1bih, xw1, FD, TH);
    }
    // 8
    gru1d_kernel<<<Bb, Hh>>>(g1bhh);
    // 9
    finalg_kernel<<<Bb, 256>>>();
    // 10
    transpose_kernel<<<(Hh * GD + 255) / 256, 256>>>(fc1W, fc1Wt, Hh, GD);
    // 11
    fc1_kernel<<<Bb, Hh>>>(fc1b);
    // 12
    fc2_kernel<<<Bb, 256>>>(fc2W, fc2b, out);
}